// round 13
// baseline (speedup 1.0000x reference)
#include <cuda_runtime.h>
#include <cstdint>

#define N_PIX 87040

// ---- dynamic smem pool layout (floats) ----
//  [0      .. 6384)   lum (fp32, LR x LPAD; max 76x84)        | inv aliases (<=4160)
//  [6384   .. 15536)  RGB stage 2 x 19 x 240 (+pad)           | hT aliases (<=4864)
//  [15536  .. 15600)  sx
//  [15600  .. 15664)  sy
//  [15664  .. 15672)  4 mbarriers (u64)
#define POOL_BYTES  62720
#define OFF_RGB     6384
#define OFF_SX      15536
#define OFF_SY      15600
#define MBAR_BYTE   62656       // 15664*4

// phase 2 (32-float window, 16 outputs): element m -> output j iff j+2<=m<=j+14
#define C16(vv, m)                                                                 \
    { if ((m) >= 2  && (m) <= 14) o0  += T[(m) >= 8  ? (m)-8  : 8-(m)]  * (vv);    \
      if ((m) >= 3  && (m) <= 15) o1  += T[(m) >= 9  ? (m)-9  : 9-(m)]  * (vv);    \
      if ((m) >= 4  && (m) <= 16) o2  += T[(m) >= 10 ? (m)-10 : 10-(m)] * (vv);    \
      if ((m) >= 5  && (m) <= 17) o3  += T[(m) >= 11 ? (m)-11 : 11-(m)] * (vv);    \
      if ((m) >= 6  && (m) <= 18) o4  += T[(m) >= 12 ? (m)-12 : 12-(m)] * (vv);    \
      if ((m) >= 7  && (m) <= 19) o5  += T[(m) >= 13 ? (m)-13 : 13-(m)] * (vv);    \
      if ((m) >= 8  && (m) <= 20) o6  += T[(m) >= 14 ? (m)-14 : 14-(m)] * (vv);    \
      if ((m) >= 9  && (m) <= 21) o7  += T[(m) >= 15 ? (m)-15 : 15-(m)] * (vv);    \
      if ((m) >= 10 && (m) <= 22) o8  += T[(m) >= 16 ? (m)-16 : 16-(m)] * (vv);    \
      if ((m) >= 11 && (m) <= 23) o9  += T[(m) >= 17 ? (m)-17 : 17-(m)] * (vv);    \
      if ((m) >= 12 && (m) <= 24) o10 += T[(m) >= 18 ? (m)-18 : 18-(m)] * (vv);    \
      if ((m) >= 13 && (m) <= 25) o11 += T[(m) >= 19 ? (m)-19 : 19-(m)] * (vv);    \
      if ((m) >= 14 && (m) <= 26) o12 += T[(m) >= 20 ? (m)-20 : 20-(m)] * (vv);    \
      if ((m) >= 15 && (m) <= 27) o13 += T[(m) >= 21 ? (m)-21 : 21-(m)] * (vv);    \
      if ((m) >= 16 && (m) <= 28) o14 += T[(m) >= 22 ? (m)-22 : 22-(m)] * (vv);    \
      if ((m) >= 17 && (m) <= 29) o15 += T[(m) >= 23 ? (m)-23 : 23-(m)] * (vv); }

// phase 3a (20-float window, 8 outputs): element m -> output j iff j<=m<=j+12
#define C8V(vv, m)                                                                \
    { if ((m) <= 12)              o0 += T[(m) >= 6  ? (m)-6  : 6-(m)]  * (vv);    \
      if ((m) >= 1 && (m) <= 13)  o1 += T[(m) >= 7  ? (m)-7  : 7-(m)]  * (vv);    \
      if ((m) >= 2 && (m) <= 14)  o2 += T[(m) >= 8  ? (m)-8  : 8-(m)]  * (vv);    \
      if ((m) >= 3 && (m) <= 15)  o3 += T[(m) >= 9  ? (m)-9  : 9-(m)]  * (vv);    \
      if ((m) >= 4 && (m) <= 16)  o4 += T[(m) >= 10 ? (m)-10 : 10-(m)] * (vv);    \
      if ((m) >= 5 && (m) <= 17)  o5 += T[(m) >= 11 ? (m)-11 : 11-(m)] * (vv);    \
      if ((m) >= 6 && (m) <= 18)  o6 += T[(m) >= 12 ? (m)-12 : 12-(m)] * (vv);    \
      if ((m) >= 7 && (m) <= 19)  o7 += T[(m) >= 13 ? (m)-13 : 13-(m)] * (vv); }

__device__ __forceinline__ uint32_t smem_u32(const void* p) {
    return (uint32_t)__cvta_generic_to_shared(p);
}
__device__ __forceinline__ void mbar_init(uint32_t mbar, uint32_t cnt) {
    asm volatile("mbarrier.init.shared.b64 [%0], %1;" :: "r"(mbar), "r"(cnt) : "memory");
}
__device__ __forceinline__ void mbar_expect_tx(uint32_t mbar, uint32_t bytes) {
    asm volatile("mbarrier.arrive.expect_tx.shared.b64 _, [%0], %1;" :: "r"(mbar), "r"(bytes) : "memory");
}
__device__ __forceinline__ void mbar_wait0(uint32_t mbar) {
    asm volatile(
        "{\n\t.reg .pred P1;\n\t"
        "WAIT_LOOP_%=:\n\t"
        "mbarrier.try_wait.parity.acquire.cta.shared::cta.b64 P1, [%0], 0, 0x989680;\n\t"
        "@P1 bra.uni WAIT_DONE_%=;\n\t"
        "bra.uni WAIT_LOOP_%=;\n\t"
        "WAIT_DONE_%=:\n\t}"
        :: "r"(mbar) : "memory");
}
__device__ __forceinline__ void tma_bulk(uint32_t dst, const void* src, uint32_t bytes, uint32_t mbar) {
    asm volatile(
        "cp.async.bulk.shared::cluster.global.mbarrier::complete_tx::bytes [%0], [%1], %2, [%3];"
        :: "r"(dst), "l"(src), "r"(bytes), "r"(mbar) : "memory");
}

// W = image width (=height), TS = tile size. Compile-time only.
template<int W, int TS>
__device__ __forceinline__ void run_tile(int tloc, const float* __restrict__ base,
                                         float* __restrict__ obase,
                                         float* __restrict__ pool, int tid)
{
    const float T[7] = { 1.0f, 0.94595947f, 0.80073740f, 0.60653066f,
                         0.41111229f, 0.24935220f, 0.13533528f };
    constexpr int TPR  = W / TS;
    constexpr int LR   = TS + 12;                 // halo rows
    constexpr int LC   = TS + 16;                 // halo px cols (tx0-8 .. tx0+TS+7)
    constexpr int LPAD = (TS == 64) ? 84 : 52;    // lum row stride (floats)
    constexpr int NQ   = LC / 4;                  // 4-pixel tasks per row
    constexpr int RPW  = 3 * LC;                  // RGB row words (240 / 144)
    constexpr int RB   = RPW * 4;                 // RGB row bytes (960 / 576)
    constexpr int CHR  = LR / 4;                  // rows per chunk (19 / 11)
    constexpr int CHW  = CHR * RPW;               // chunk words
    constexpr int CHTASK = CHR * NQ;

    float* lum = pool;
    float* rgb = pool + OFF_RGB;
    float* hT  = pool + OFF_RGB;                  // aliases RGB (dead after P1)
    float* sxs = pool + OFF_SX;
    float* sys = pool + OFF_SY;
    float* inv = pool;                            // aliases lum (dead after P2)

    const int tx0 = (tloc & (TPR - 1)) * TS;
    const int ty0 = (tloc / TPR) * TS;
    const uint32_t mbar0 = smem_u32((const char*)pool + (MBAR_BYTE - 0) + 0) - (MBAR_BYTE - MBAR_BYTE);
    const uint32_t mb    = smem_u32((const char*)pool) + MBAR_BYTE;   // byte address of mbar[0]
    const uint32_t rgb0  = smem_u32(rgb);

    constexpr int HIB = 12 * W * W - RB;          // max row-start byte offset (level-local)

    // ---- init mbarriers + dens tables ----
    if (tid == 0) {
#pragma unroll
        for (int k = 0; k < 4; k++) mbar_init(mb + 8 * k, 1);
    }
    if (tid < 2 * TS) {
        int p = tid & (TS - 1);
        int g = (tid < TS ? tx0 : ty0) + p;
        float s = T[0];
        s += (g >= 1 ? T[1] : 0.f) + (g >= 2 ? T[2] : 0.f) + (g >= 3 ? T[3] : 0.f)
           + (g >= 4 ? T[4] : 0.f) + (g >= 5 ? T[5] : 0.f) + (g >= 6 ? T[6] : 0.f);
        int d = W - 1 - g;
        s += (d >= 1 ? T[1] : 0.f) + (d >= 2 ? T[2] : 0.f) + (d >= 3 ? T[3] : 0.f)
           + (d >= 4 ? T[4] : 0.f) + (d >= 5 ? T[5] : 0.f) + (d >= 6 ? T[6] : 0.f);
        if (tid < TS) sxs[p] = s; else sys[p] = s;
    }
    __syncthreads();

    const bool interior = (tx0 >= 8) && (ty0 >= 6) &&
                          (tx0 + TS + 8 <= W) && (ty0 + TS + 6 <= W);

    // ---- TMA issue helper (chunk k -> buffer k&1) ----
    auto issue_chunk = [&](int k) {
        mbar_expect_tx(mb + 8 * k, (uint32_t)(CHR * RB));
        uint32_t dst = rgb0 + (uint32_t)((k & 1) * CHW * 4);
        int rg0 = k * CHR;
#pragma unroll 4
        for (int i = 0; i < CHR; i++) {
            int gy = ty0 - 6 + rg0 + i;
            int u  = (gy * W + tx0 - 8) * 12;
            u = min(max(u, 0), HIB);
            tma_bulk(dst + (uint32_t)(i * RB), (const char*)base + u, (uint32_t)RB, mb + 8 * k);
        }
    };

    if (tid == 0) { issue_chunk(0); issue_chunk(1); }

    // ---- phase 1: per-chunk luminance from staged RGB ----
#pragma unroll
    for (int k = 0; k < 4; k++) {
        mbar_wait0(mb + 8 * k);
        if (tid < CHTASK) {
            int i = tid / NQ;
            int q = tid - i * NQ;
            int rg = k * CHR + i;
            const float* row = rgb + (k & 1) * CHW + i * RPW;
            if (interior) {
                float4 a = *(const float4*)(row + 12 * q);
                float4 b = *(const float4*)(row + 12 * q + 4);
                float4 c = *(const float4*)(row + 12 * q + 8);
                float4 o;
                o.x = 0.2989f * a.x + 0.587f * a.y + 0.114f * a.z;
                o.y = 0.2989f * a.w + 0.587f * b.x + 0.114f * b.y;
                o.z = 0.2989f * b.z + 0.587f * b.w + 0.114f * c.x;
                o.w = 0.2989f * c.y + 0.587f * c.z + 0.114f * c.w;
                *(float4*)&lum[rg * LPAD + 4 * q] = o;
            } else {
                int gy  = ty0 - 6 + rg;
                bool ry = (unsigned)gy < (unsigned)W;
                int u_raw = (gy * W + tx0 - 8) * 12;
                int u_c   = min(max(u_raw, 0), HIB);
                int sh    = ry ? ((u_raw - u_c) >> 2) : 0;   // float shift in {-24,0,+24}
                int idx   = 12 * q + sh;
                float4 a = *(const float4*)(row + idx);
                float4 b = *(const float4*)(row + idx + 4);
                float4 c = *(const float4*)(row + idx + 8);
                int gx0 = tx0 - 8 + 4 * q;
                float4 o;
                o.x = (ry && (unsigned)(gx0    ) < (unsigned)W) ? (0.2989f * a.x + 0.587f * a.y + 0.114f * a.z) : 0.f;
                o.y = (ry && (unsigned)(gx0 + 1) < (unsigned)W) ? (0.2989f * a.w + 0.587f * b.x + 0.114f * b.y) : 0.f;
                o.z = (ry && (unsigned)(gx0 + 2) < (unsigned)W) ? (0.2989f * b.z + 0.587f * b.w + 0.114f * c.x) : 0.f;
                o.w = (ry && (unsigned)(gx0 + 3) < (unsigned)W) ? (0.2989f * c.y + 0.587f * c.z + 0.114f * c.w) : 0.f;
                *(float4*)&lum[rg * LPAD + 4 * q] = o;
            }
        }
        __syncthreads();
        if (k < 2 && tid == 0) issue_chunk(k + 2);
    }

    // ---- phase 2: horizontal blur; 16 outputs/thread via 8 aligned LDS.128 ----
    {
        constexpr int NG = TS / 16;
        constexpr int NT = NG * LR;
        for (int t = tid; t < NT; t += 512) {
            int g = t / LR;
            int r = t - g * LR;
            const float* row = &lum[r * LPAD + g * 16];
            float o0  = 0.f, o1  = 0.f, o2  = 0.f, o3  = 0.f;
            float o4  = 0.f, o5  = 0.f, o6  = 0.f, o7  = 0.f;
            float o8  = 0.f, o9  = 0.f, o10 = 0.f, o11 = 0.f;
            float o12 = 0.f, o13 = 0.f, o14 = 0.f, o15 = 0.f;
#pragma unroll
            for (int kk = 0; kk < 8; kk++) {
                float4 qv = *(const float4*)(row + 4 * kk);
                C16(qv.x, 4 * kk + 0);
                C16(qv.y, 4 * kk + 1);
                C16(qv.z, 4 * kk + 2);
                C16(qv.w, 4 * kk + 3);
            }
            float* dst = &hT[(g * 16) * LR + r];
            dst[ 0 * LR] = o0;  dst[ 1 * LR] = o1;  dst[ 2 * LR] = o2;  dst[ 3 * LR] = o3;
            dst[ 4 * LR] = o4;  dst[ 5 * LR] = o5;  dst[ 6 * LR] = o6;  dst[ 7 * LR] = o7;
            dst[ 8 * LR] = o8;  dst[ 9 * LR] = o9;  dst[10 * LR] = o10; dst[11 * LR] = o11;
            dst[12 * LR] = o12; dst[13 * LR] = o13; dst[14 * LR] = o14; dst[15 * LR] = o15;
        }
    }
    __syncthreads();

    // ---- phase 3a: vertical blur; 8 rows/thread via 5 aligned LDS.128; dens ----
    {
        constexpr int NT = TS * (TS / 8);
        for (int t = tid; t < NT; t += 512) {
            int c  = t & (TS - 1);
            int r0 = (t / TS) << 3;
            const float* colp = &hT[c * LR + r0];
            float o0 = 0.f, o1 = 0.f, o2 = 0.f, o3 = 0.f;
            float o4 = 0.f, o5 = 0.f, o6 = 0.f, o7 = 0.f;
#pragma unroll
            for (int kk = 0; kk < 5; kk++) {
                float4 qv = *(const float4*)(colp + 4 * kk);
                C8V(qv.x, 4 * kk + 0);
                C8V(qv.y, 4 * kk + 1);
                C8V(qv.z, 4 * kk + 2);
                C8V(qv.w, 4 * kk + 3);
            }
            const float sx = sxs[c];
            float* invp = &inv[r0 * (TS + 1) + c];
#pragma unroll
            for (int j = 0; j < 8; j++) {
                float oj = (j == 0) ? o0 : (j == 1) ? o1 : (j == 2) ? o2 : (j == 3) ? o3
                         : (j == 4) ? o4 : (j == 5) ? o5 : (j == 6) ? o6 : o7;
                float dj = 0.9999f * sys[r0 + j] * sx;
                invp[j * (TS + 1)] = __fdividef(dj, oj + 1e-3f * dj);
            }
        }
    }
    __syncthreads();

    // ---- phase 3b: vectorized divide; TS rows x (TS*3/4) float4 ----
    {
        constexpr int FPR = TS * 3 / 4;
        constexpr int NT  = TS * FPR;
        for (int t = tid; t < NT; t += 512) {
            int row = (TS == 64) ? (((t >> 4) * 21846) >> 16)
                                 : (((t >> 3) * 21846) >> 16);
            int f   = t - row * FPR;
            int u   = f << 2;
            int p0  = (u * 21846) >> 16;
            int fm3 = u - 3 * p0;
            int th  = 3 - fm3;

            const float* invrow = &inv[row * (TS + 1)];
            float iA = invrow[p0];
            float iB = invrow[p0 + 1];

            int goff = ((ty0 + row) * W + tx0) * 3 + u;
            float4 qv = *(const float4*)(base + goff);
            qv.x *= iA;
            qv.y *= (1 < th) ? iA : iB;
            qv.z *= (2 < th) ? iA : iB;
            qv.w *= iB;
            *(float4*)(obase + goff) = qv;
        }
    }
}

__global__ __launch_bounds__(512, 3)
void lln_kernel(const float* __restrict__ x, float* __restrict__ out)
{
    extern __shared__ float pool[];
    const int tile = blockIdx.x;   // 0..21
    const int b    = blockIdx.y;
    const int tid  = threadIdx.x;
    const int bo   = b * (N_PIX * 3);

    if (tile < 16) {
        run_tile<256, 64>(tile,      x + bo,             out + bo,             pool, tid);
    } else if (tile < 20) {
        run_tile<128, 64>(tile - 16, x + bo + 65536 * 3, out + bo + 65536 * 3, pool, tid);
    } else if (tile == 20) {
        run_tile<64, 64> (0,         x + bo + 81920 * 3, out + bo + 81920 * 3, pool, tid);
    } else {
        run_tile<32, 32> (0,         x + bo + 86016 * 3, out + bo + 86016 * 3, pool, tid);
    }
}

extern "C" void kernel_launch(void* const* d_in, const int* in_sizes, int n_in,
                              void* d_out, int out_size)
{
    const float* x = (const float*)d_in[0];
    float* out     = (float*)d_out;
    cudaFuncSetAttribute(lln_kernel, cudaFuncAttributeMaxDynamicSharedMemorySize, POOL_BYTES);
    dim3 grid(22, 128);
    lln_kernel<<<grid, 512, POOL_BYTES>>>(x, out);
}

// round 15
// speedup vs baseline: 1.0941x; 1.0941x over previous
#include <cuda_runtime.h>
#include <cstdint>

#define N_PIX 87040

// ---- dynamic smem pool layout (floats) ----
//  [0     .. 6384)   lum (LR x LPAD; max 76x84)     | inv aliases (<=4160)
//  [6384  .. 12624)  RGB stage 2 x 13 x 240         | hT aliases (<=4864)
//  [12624 .. 12688)  sx
//  [12688 .. 12752)  sy
//  byte 51008:       6 mbarriers (u64)
#define OFF_RGB     6384
#define OFF_SX      12624
#define OFF_SY      12688
#define MBAR_BYTE   51008
#define POOL_BYTES  51072

// phase 2 (32-float window, 16 outputs): element m -> output j iff j+2<=m<=j+14
#define C16(vv, m)                                                                 \
    { if ((m) >= 2  && (m) <= 14) o0  += T[(m) >= 8  ? (m)-8  : 8-(m)]  * (vv);    \
      if ((m) >= 3  && (m) <= 15) o1  += T[(m) >= 9  ? (m)-9  : 9-(m)]  * (vv);    \
      if ((m) >= 4  && (m) <= 16) o2  += T[(m) >= 10 ? (m)-10 : 10-(m)] * (vv);    \
      if ((m) >= 5  && (m) <= 17) o3  += T[(m) >= 11 ? (m)-11 : 11-(m)] * (vv);    \
      if ((m) >= 6  && (m) <= 18) o4  += T[(m) >= 12 ? (m)-12 : 12-(m)] * (vv);    \
      if ((m) >= 7  && (m) <= 19) o5  += T[(m) >= 13 ? (m)-13 : 13-(m)] * (vv);    \
      if ((m) >= 8  && (m) <= 20) o6  += T[(m) >= 14 ? (m)-14 : 14-(m)] * (vv);    \
      if ((m) >= 9  && (m) <= 21) o7  += T[(m) >= 15 ? (m)-15 : 15-(m)] * (vv);    \
      if ((m) >= 10 && (m) <= 22) o8  += T[(m) >= 16 ? (m)-16 : 16-(m)] * (vv);    \
      if ((m) >= 11 && (m) <= 23) o9  += T[(m) >= 17 ? (m)-17 : 17-(m)] * (vv);    \
      if ((m) >= 12 && (m) <= 24) o10 += T[(m) >= 18 ? (m)-18 : 18-(m)] * (vv);    \
      if ((m) >= 13 && (m) <= 25) o11 += T[(m) >= 19 ? (m)-19 : 19-(m)] * (vv);    \
      if ((m) >= 14 && (m) <= 26) o12 += T[(m) >= 20 ? (m)-20 : 20-(m)] * (vv);    \
      if ((m) >= 15 && (m) <= 27) o13 += T[(m) >= 21 ? (m)-21 : 21-(m)] * (vv);    \
      if ((m) >= 16 && (m) <= 28) o14 += T[(m) >= 22 ? (m)-22 : 22-(m)] * (vv);    \
      if ((m) >= 17 && (m) <= 29) o15 += T[(m) >= 23 ? (m)-23 : 23-(m)] * (vv); }

// phase 3a (20-float window, 8 outputs): element m -> output j iff j<=m<=j+12
#define C8V(vv, m)                                                                \
    { if ((m) <= 12)              o0 += T[(m) >= 6  ? (m)-6  : 6-(m)]  * (vv);    \
      if ((m) >= 1 && (m) <= 13)  o1 += T[(m) >= 7  ? (m)-7  : 7-(m)]  * (vv);    \
      if ((m) >= 2 && (m) <= 14)  o2 += T[(m) >= 8  ? (m)-8  : 8-(m)]  * (vv);    \
      if ((m) >= 3 && (m) <= 15)  o3 += T[(m) >= 9  ? (m)-9  : 9-(m)]  * (vv);    \
      if ((m) >= 4 && (m) <= 16)  o4 += T[(m) >= 10 ? (m)-10 : 10-(m)] * (vv);    \
      if ((m) >= 5 && (m) <= 17)  o5 += T[(m) >= 11 ? (m)-11 : 11-(m)] * (vv);    \
      if ((m) >= 6 && (m) <= 18)  o6 += T[(m) >= 12 ? (m)-12 : 12-(m)] * (vv);    \
      if ((m) >= 7 && (m) <= 19)  o7 += T[(m) >= 13 ? (m)-13 : 13-(m)] * (vv); }

__device__ __forceinline__ uint32_t smem_u32(const void* p) {
    return (uint32_t)__cvta_generic_to_shared(p);
}
__device__ __forceinline__ void mbar_init(uint32_t mbar, uint32_t cnt) {
    asm volatile("mbarrier.init.shared.b64 [%0], %1;" :: "r"(mbar), "r"(cnt) : "memory");
}
__device__ __forceinline__ void mbar_expect_tx(uint32_t mbar, uint32_t bytes) {
    asm volatile("mbarrier.arrive.expect_tx.shared.b64 _, [%0], %1;" :: "r"(mbar), "r"(bytes) : "memory");
}
__device__ __forceinline__ void mbar_wait0(uint32_t mbar) {
    asm volatile(
        "{\n\t.reg .pred P1;\n\t"
        "WAIT_LOOP_%=:\n\t"
        "mbarrier.try_wait.parity.acquire.cta.shared::cta.b64 P1, [%0], 0, 0x989680;\n\t"
        "@P1 bra.uni WAIT_DONE_%=;\n\t"
        "bra.uni WAIT_LOOP_%=;\n\t"
        "WAIT_DONE_%=:\n\t}"
        :: "r"(mbar) : "memory");
}
__device__ __forceinline__ void tma_bulk(uint32_t dst, const void* src, uint32_t bytes, uint32_t mbar) {
    asm volatile(
        "cp.async.bulk.shared::cluster.global.mbarrier::complete_tx::bytes [%0], [%1], %2, [%3];"
        :: "r"(dst), "l"(src), "r"(bytes), "r"(mbar) : "memory");
}

// W = image width (=height), TS = tile size. Compile-time only.
template<int W, int TS>
__device__ __forceinline__ void run_tile(int tloc, const float* __restrict__ base,
                                         float* __restrict__ obase,
                                         float* __restrict__ pool, int tid)
{
    const float T[7] = { 1.0f, 0.94595947f, 0.80073740f, 0.60653066f,
                         0.41111229f, 0.24935220f, 0.13533528f };
    constexpr int TPR  = W / TS;
    constexpr int LR   = TS + 12;                 // halo rows (76 / 44)
    constexpr int LC   = TS + 16;                 // halo px cols
    constexpr int LPAD = (TS == 64) ? 84 : 52;    // lum row stride (floats)
    constexpr int NQ   = LC / 4;                  // 4-pixel tasks per row (20 / 12)
    constexpr int RPW  = 3 * LC;                  // RGB row words (240 / 144)
    constexpr int RB   = RPW * 4;                 // RGB row bytes (960 / 576)
    constexpr int CHR  = (TS == 64) ? 13 : 11;    // rows per chunk
    constexpr int NCH  = (LR + CHR - 1) / CHR;    // chunks (6 / 4)
    constexpr int BUFW = CHR * RPW;               // buffer words

    float* lum = pool;
    float* rgb = pool + OFF_RGB;
    float* hT  = pool + OFF_RGB;                  // aliases RGB (dead after P1)
    float* sxs = pool + OFF_SX;
    float* sys = pool + OFF_SY;
    float* inv = pool;                            // aliases lum (dead after P2)

    const int tx0 = (tloc & (TPR - 1)) * TS;
    const int ty0 = (tloc / TPR) * TS;
    const uint32_t mb   = smem_u32((const char*)pool) + MBAR_BYTE;
    const uint32_t rgb0 = smem_u32(rgb);

    constexpr int HIB = 12 * W * W - RB;          // max row-start byte offset

    if (tid == 0) {
#pragma unroll
        for (int k = 0; k < NCH; k++) mbar_init(mb + 8 * k, 1);
    }
    if (tid < 2 * TS) {
        int p = tid & (TS - 1);
        int g = (tid < TS ? tx0 : ty0) + p;
        float s = T[0];
        s += (g >= 1 ? T[1] : 0.f) + (g >= 2 ? T[2] : 0.f) + (g >= 3 ? T[3] : 0.f)
           + (g >= 4 ? T[4] : 0.f) + (g >= 5 ? T[5] : 0.f) + (g >= 6 ? T[6] : 0.f);
        int d = W - 1 - g;
        s += (d >= 1 ? T[1] : 0.f) + (d >= 2 ? T[2] : 0.f) + (d >= 3 ? T[3] : 0.f)
           + (d >= 4 ? T[4] : 0.f) + (d >= 5 ? T[5] : 0.f) + (d >= 6 ? T[6] : 0.f);
        if (tid < TS) sxs[p] = s; else sys[p] = s;
    }
    __syncthreads();

    const bool interior = (tx0 >= 8) && (ty0 >= 6) &&
                          (tx0 + TS + 8 <= W) && (ty0 + TS + 6 <= W);

    auto issue_chunk = [&](int k) {
        int rows = min(CHR, LR - k * CHR);
        mbar_expect_tx(mb + 8 * k, (uint32_t)(rows * RB));
        uint32_t dst = rgb0 + (uint32_t)((k & 1) * BUFW * 4);
        int rg0 = k * CHR;
        for (int i = 0; i < rows; i++) {
            int gy = ty0 - 6 + rg0 + i;
            int u  = (gy * W + tx0 - 8) * 12;
            u = min(max(u, 0), HIB);
            tma_bulk(dst + (uint32_t)(i * RB), (const char*)base + u, (uint32_t)RB, mb + 8 * k);
        }
    };

    if (tid == 0) { issue_chunk(0); issue_chunk(1); }

    // ---- phase 1: per-chunk luminance from staged RGB ----
#pragma unroll
    for (int k = 0; k < NCH; k++) {
        int rows = min(CHR, LR - k * CHR);
        mbar_wait0(mb + 8 * k);
        if (tid < rows * NQ) {
            int i = tid / NQ;
            int q = tid - i * NQ;
            int rg = k * CHR + i;
            const float* row = rgb + (k & 1) * BUFW + i * RPW;
            if (interior) {
                float4 a = *(const float4*)(row + 12 * q);
                float4 b = *(const float4*)(row + 12 * q + 4);
                float4 c = *(const float4*)(row + 12 * q + 8);
                float4 o;
                o.x = 0.2989f * a.x + 0.587f * a.y + 0.114f * a.z;
                o.y = 0.2989f * a.w + 0.587f * b.x + 0.114f * b.y;
                o.z = 0.2989f * b.z + 0.587f * b.w + 0.114f * c.x;
                o.w = 0.2989f * c.y + 0.587f * c.z + 0.114f * c.w;
                *(float4*)&lum[rg * LPAD + 4 * q] = o;
            } else {
                int gy  = ty0 - 6 + rg;
                bool ry = (unsigned)gy < (unsigned)W;
                int u_raw = (gy * W + tx0 - 8) * 12;
                int u_c   = min(max(u_raw, 0), HIB);
                int sh    = ry ? ((u_raw - u_c) >> 2) : 0;
                int idx   = 12 * q + sh;
                float4 a = *(const float4*)(row + idx);
                float4 b = *(const float4*)(row + idx + 4);
                float4 c = *(const float4*)(row + idx + 8);
                int gx0 = tx0 - 8 + 4 * q;
                float4 o;
                o.x = (ry && (unsigned)(gx0    ) < (unsigned)W) ? (0.2989f * a.x + 0.587f * a.y + 0.114f * a.z) : 0.f;
                o.y = (ry && (unsigned)(gx0 + 1) < (unsigned)W) ? (0.2989f * a.w + 0.587f * b.x + 0.114f * b.y) : 0.f;
                o.z = (ry && (unsigned)(gx0 + 2) < (unsigned)W) ? (0.2989f * b.z + 0.587f * b.w + 0.114f * c.x) : 0.f;
                o.w = (ry && (unsigned)(gx0 + 3) < (unsigned)W) ? (0.2989f * c.y + 0.587f * c.z + 0.114f * c.w) : 0.f;
                *(float4*)&lum[rg * LPAD + 4 * q] = o;
            }
        }
        __syncthreads();
        if (k + 2 < NCH && tid == 0) issue_chunk(k + 2);
    }

    // ---- phase 2: horizontal blur; 16 outputs/thread via 8 aligned LDS.128 ----
    {
        constexpr int NG = TS / 16;
        constexpr int NT = NG * LR;
        for (int t = tid; t < NT; t += 512) {
            int g = t / LR;
            int r = t - g * LR;
            const float* row = &lum[r * LPAD + g * 16];
            float o0  = 0.f, o1  = 0.f, o2  = 0.f, o3  = 0.f;
            float o4  = 0.f, o5  = 0.f, o6  = 0.f, o7  = 0.f;
            float o8  = 0.f, o9  = 0.f, o10 = 0.f, o11 = 0.f;
            float o12 = 0.f, o13 = 0.f, o14 = 0.f, o15 = 0.f;
#pragma unroll
            for (int kk = 0; kk < 8; kk++) {
                float4 qv = *(const float4*)(row + 4 * kk);
                C16(qv.x, 4 * kk + 0);
                C16(qv.y, 4 * kk + 1);
                C16(qv.z, 4 * kk + 2);
                C16(qv.w, 4 * kk + 3);
            }
            float* dst = &hT[(g * 16) * LR + r];
            dst[ 0 * LR] = o0;  dst[ 1 * LR] = o1;  dst[ 2 * LR] = o2;  dst[ 3 * LR] = o3;
            dst[ 4 * LR] = o4;  dst[ 5 * LR] = o5;  dst[ 6 * LR] = o6;  dst[ 7 * LR] = o7;
            dst[ 8 * LR] = o8;  dst[ 9 * LR] = o9;  dst[10 * LR] = o10; dst[11 * LR] = o11;
            dst[12 * LR] = o12; dst[13 * LR] = o13; dst[14 * LR] = o14; dst[15 * LR] = o15;
        }
    }
    __syncthreads();

    // ---- phase 3a: vertical blur; 8 rows/thread via 5 aligned LDS.128; dens ----
    {
        constexpr int NT = TS * (TS / 8);
        for (int t = tid; t < NT; t += 512) {
            int c  = t & (TS - 1);
            int r0 = (t / TS) << 3;
            const float* colp = &hT[c * LR + r0];
            float o0 = 0.f, o1 = 0.f, o2 = 0.f, o3 = 0.f;
            float o4 = 0.f, o5 = 0.f, o6 = 0.f, o7 = 0.f;
#pragma unroll
            for (int kk = 0; kk < 5; kk++) {
                float4 qv = *(const float4*)(colp + 4 * kk);
                C8V(qv.x, 4 * kk + 0);
                C8V(qv.y, 4 * kk + 1);
                C8V(qv.z, 4 * kk + 2);
                C8V(qv.w, 4 * kk + 3);
            }
            const float sx = sxs[c];
            float* invp = &inv[r0 * (TS + 1) + c];
#pragma unroll
            for (int j = 0; j < 8; j++) {
                float oj = (j == 0) ? o0 : (j == 1) ? o1 : (j == 2) ? o2 : (j == 3) ? o3
                         : (j == 4) ? o4 : (j == 5) ? o5 : (j == 6) ? o6 : o7;
                float dj = 0.9999f * sys[r0 + j] * sx;
                invp[j * (TS + 1)] = __fdividef(dj, oj + 1e-3f * dj);
            }
        }
    }
    __syncthreads();

    // ---- phase 3b: vectorized divide; TS rows x (TS*3/4) float4 ----
    {
        constexpr int FPR = TS * 3 / 4;
        constexpr int NT  = TS * FPR;
        for (int t = tid; t < NT; t += 512) {
            int row = (TS == 64) ? (((t >> 4) * 21846) >> 16)
                                 : (((t >> 3) * 21846) >> 16);
            int f   = t - row * FPR;
            int u   = f << 2;
            int p0  = (u * 21846) >> 16;
            int fm3 = u - 3 * p0;
            int th  = 3 - fm3;

            const float* invrow = &inv[row * (TS + 1)];
            float iA = invrow[p0];
            float iB = invrow[p0 + 1];

            int goff = ((ty0 + row) * W + tx0) * 3 + u;
            float4 qv = *(const float4*)(base + goff);
            qv.x *= iA;
            qv.y *= (1 < th) ? iA : iB;
            qv.z *= (2 < th) ? iA : iB;
            qv.w *= iB;
            *(float4*)(obase + goff) = qv;
        }
    }
}

__global__ __launch_bounds__(512, 4)
void lln_kernel(const float* __restrict__ x, float* __restrict__ out)
{
    extern __shared__ float pool[];
    const int tile = blockIdx.x;   // 0..21
    const int b    = blockIdx.y;
    const int tid  = threadIdx.x;
    const int bo   = b * (N_PIX * 3);

    if (tile < 16) {
        run_tile<256, 64>(tile,      x + bo,             out + bo,             pool, tid);
    } else if (tile < 20) {
        run_tile<128, 64>(tile - 16, x + bo + 65536 * 3, out + bo + 65536 * 3, pool, tid);
    } else if (tile == 20) {
        run_tile<64, 64> (0,         x + bo + 81920 * 3, out + bo + 81920 * 3, pool, tid);
    } else {
        run_tile<32, 32> (0,         x + bo + 86016 * 3, out + bo + 86016 * 3, pool, tid);
    }
}

extern "C" void kernel_launch(void* const* d_in, const int* in_sizes, int n_in,
                              void* d_out, int out_size)
{
    const float* x = (const float*)d_in[0];
    float* out     = (float*)d_out;
    cudaFuncSetAttribute(lln_kernel, cudaFuncAttributeMaxDynamicSharedMemorySize, POOL_BYTES);
    dim3 grid(22, 128);
    lln_kernel<<<grid, 512, POOL_BYTES>>>(x, out);
}